// round 12
// baseline (speedup 1.0000x reference)
#include <cuda_runtime.h>
#include <cuda_fp16.h>
#include <cstdint>

#define BB   8
#define SS   4096
#define DIN  512
#define DD   256

// ---------------------------------------------------------------------------
// Global scratch (static __device__ arrays: no allocation)
// ---------------------------------------------------------------------------
__device__ __half gx[BB * SS * DIN];
__device__ __half gWq[DIN * DD], gWk[DIN * DD], gWv[DIN * DD];
__device__ __half gQ[BB * SS * DD], gK[BB * SS * DD], gV[BB * SS * DD];
__device__ float gOp[3][BB * SS * DD];   // O partials for k-quarters 0..2
__device__ float gLp[3][BB * SS];        // l partials
__device__ int   wDone[3];               // W convert counters (target 4)
__device__ int   xDone[BB];              // x convert counters (target 32)
__device__ int   projDone[BB];           // per-batch proj counters (target 96)
__device__ int   tileDone[256];          // per-qtile flash partial counters

// unit layout in mega's grid
#define N_WU 12
#define N_XU 256
#define N_PU 768
#define N_FU 1024
#define GRID_MEGA (N_WU + N_XU + N_PU + N_FU)   // 2060

// ---------------------------------------------------------------------------
// helpers
// ---------------------------------------------------------------------------
__device__ __forceinline__ uint32_t smem_u32(const void* p) {
    uint32_t a;
    asm("{ .reg .u64 t; cvta.to.shared.u64 t, %1; cvt.u32.u64 %0, t; }"
        : "=r"(a) : "l"(p));
    return a;
}
__device__ __forceinline__ void ldsm4(uint32_t a, uint32_t r[4]) {
    asm volatile("ldmatrix.sync.aligned.m8n8.x4.shared.b16 {%0,%1,%2,%3}, [%4];"
        : "=r"(r[0]), "=r"(r[1]), "=r"(r[2]), "=r"(r[3]) : "r"(a));
}
__device__ __forceinline__ void ldsm4t(uint32_t a, uint32_t r[4]) {
    asm volatile("ldmatrix.sync.aligned.m8n8.x4.trans.shared.b16 {%0,%1,%2,%3}, [%4];"
        : "=r"(r[0]), "=r"(r[1]), "=r"(r[2]), "=r"(r[3]) : "r"(a));
}
__device__ __forceinline__ void mma_f16(float c[4], const uint32_t a[4],
                                        uint32_t b0, uint32_t b1) {
    asm volatile(
        "mma.sync.aligned.m16n8k16.row.col.f32.f16.f16.f32 "
        "{%0,%1,%2,%3}, {%4,%5,%6,%7}, {%8,%9}, {%0,%1,%2,%3};"
        : "+f"(c[0]), "+f"(c[1]), "+f"(c[2]), "+f"(c[3])
        : "r"(a[0]), "r"(a[1]), "r"(a[2]), "r"(a[3]), "r"(b0), "r"(b1));
}
__device__ __forceinline__ float ex2(float x) {
    float r;
    asm("ex2.approx.f32 %0, %1;" : "=f"(r) : "f"(x));
    return r;
}
__device__ __forceinline__ uint32_t h2u(__half2 h) {
    return *reinterpret_cast<uint32_t*>(&h);
}
__device__ __forceinline__ void cpa16(uint32_t s, const void* g) {
    asm volatile("cp.async.cg.shared.global [%0], [%1], 16;" :: "r"(s), "l"(g));
}
#define CP_COMMIT() asm volatile("cp.async.commit_group;" ::: "memory")
#define CP_WAIT1()  asm volatile("cp.async.wait_group 1;" ::: "memory")
#define CP_WAIT0()  asm volatile("cp.async.wait_group 0;" ::: "memory")

__device__ __forceinline__ void spin_on(volatile int* ctr, int target) {
    while (*ctr < target) __nanosleep(128);
}

// ---------------------------------------------------------------------------
// Kernel 0: zero the flow counters (runs before mega each replay).
// ---------------------------------------------------------------------------
__global__ void zero_init()
{
    int t = threadIdx.x;
    tileDone[t] = 0;
    if (t < 3)  wDone[t] = 0;
    if (t < BB) { xDone[t] = 0; projDone[t] = 0; }
}

// ---------------------------------------------------------------------------
// Fused mega-kernel. grid = 2060 CTAs, 256 thr, 192KB smem.
//   bid [0,12):        W convert units: yb=bid/4, quarter=bid%4 -> wDone[yb]
//   bid [12,268):      x convert units: u=bid-12, b=u/32, chunk -> xDone[b]
//   bid [268,1036):    proj units (b, yb, xt); spin wDone[yb]==4, xDone[b]==32
//   bid [1036,2060):   flash units: kq=fid/256, tile=fid%256; spin projDone
// Every spinner waits only on strictly-lower-bid CTAs (in-order dispatch).
// ---------------------------------------------------------------------------
#define MEGA_SMEM 196608
// proj smem layout
#define PJ_W0     32768
#define PJ_XSTG   16384
#define PJ_WSTG   32768
// flash smem layout
#define FL_K0     65536
#define FL_V0     131072
#define FL_STG    32768

#define NW4  (DIN * DD / 4)      // 32768 f4 per weight
#define NXB4 (SS * DIN / 4)      // 524288 f4 per batch of x

__device__ __forceinline__ void proj_issue(uint32_t sb, int st, int kb,
                                           const __half* xg, const __half* Wg,
                                           int tid)
{
    #pragma unroll
    for (int t = 0; t < 4; t++) {
        int idx = tid + t * 256;
        int r = idx >> 3, c = idx & 7;
        cpa16(sb + st * PJ_XSTG + (uint32_t)(r * 128 + ((c ^ (r & 7)) << 4)),
              xg + (size_t)r * DIN + kb * 64 + c * 8);
    }
    #pragma unroll
    for (int t = 0; t < 8; t++) {
        int idx = tid + t * 256;
        int r = idx >> 5, c = idx & 31;
        cpa16(sb + PJ_W0 + st * PJ_WSTG + (uint32_t)(r * 512 + ((c ^ (r & 7)) << 4)),
              Wg + (size_t)(kb * 64 + r) * DD + c * 8);
    }
    CP_COMMIT();
}

__device__ __forceinline__ void kv_issue_nc(uint32_t sb, int st,
                                            const __half* Kg, const __half* Vg,
                                            int tid)
{
    #pragma unroll
    for (int t = 0; t < 8; t++) {
        int idx = tid + t * 256;
        int r = idx >> 5, c = idx & 31;
        uint32_t off = (uint32_t)(r * 512 + ((c ^ (r & 7)) << 4));
        cpa16(sb + FL_K0 + st * FL_STG + off, Kg + (size_t)r * DD + c * 8);
        cpa16(sb + FL_V0 + st * FL_STG + off, Vg + (size_t)r * DD + c * 8);
    }
}

__global__ __launch_bounds__(256, 1) void mega(
    const float* __restrict__ x,
    const float* __restrict__ Wq, const float* __restrict__ bq,
    const float* __restrict__ Wk, const float* __restrict__ bk,
    const float* __restrict__ Wv, const float* __restrict__ bv,
    float* __restrict__ out)
{
    extern __shared__ char sm[];
    const uint32_t sb = smem_u32(sm);
    const int bid = blockIdx.x;
    const int tid = threadIdx.x;
    const int w   = tid >> 5;
    const int l   = tid & 31;
    const int grp = l >> 2, tid4 = l & 3;

    if (bid < N_WU) {
        // ==================== W CONVERT UNIT ====================
        const int yb = bid >> 2;
        const int qt = bid & 3;
        const float* src = (yb == 0) ? Wq : (yb == 1) ? Wk : Wv;
        __half* dst      = (yb == 0) ? gWq : (yb == 1) ? gWk : gWv;
        const int base = qt * (NW4 / 4);          // 8192 f4 per quarter
        #pragma unroll 4
        for (int i = tid; i < NW4 / 4; i += 256) {
            float4 v = ((const float4*)src)[base + i];
            __half2 a = __floats2half2_rn(v.x, v.y);
            __half2 b = __floats2half2_rn(v.z, v.w);
            ((uint2*)dst)[base + i] = make_uint2(h2u(a), h2u(b));
        }
        __threadfence();
        __syncthreads();
        if (tid == 0) atomicAdd(&wDone[yb], 1);
        return;
    }

    if (bid < N_WU + N_XU) {
        // ==================== X CONVERT UNIT ====================
        const int u  = bid - N_WU;
        const int bb = u >> 5;
        const int ch = u & 31;
        const int base = bb * NXB4 + ch * (NXB4 / 32);   // 16384 f4 per chunk
        #pragma unroll 4
        for (int i = tid; i < NXB4 / 32; i += 256) {
            float4 v = ((const float4*)x)[base + i];
            __half2 a = __floats2half2_rn(v.x, v.y);
            __half2 c = __floats2half2_rn(v.z, v.w);
            ((uint2*)gx)[base + i] = make_uint2(h2u(a), h2u(c));
        }
        __threadfence();
        __syncthreads();
        if (tid == 0) atomicAdd(&xDone[bb], 1);
        return;
    }

    if (bid < N_WU + N_XU + N_PU) {
        // ==================== PROJ UNIT ====================
        const int pid = bid - (N_WU + N_XU);
        const int bb = pid / 96;
        const int r96 = pid - bb * 96;
        const int yb = r96 >> 5;
        const int xt = r96 & 31;
        const int m0 = (bb * 32 + xt) * 128;

        const __half* W    = (yb == 0) ? gWq : (yb == 1) ? gWk : gWv;
        const float*  bias = (yb == 0) ? bq  : (yb == 1) ? bk  : bv;
        __half*       O    = (yb == 0) ? gQ  : (yb == 1) ? gK  : gV;
        const float scl = (yb == 0) ? 0.09014205f : 1.0f;  // log2(e)/16

        // wait for this weight + this batch's x (producers all lower-bid)
        if (tid == 0) {
            spin_on(wDone + yb, 4);
            spin_on(xDone + bb, 32);
            __threadfence();
        }
        __syncthreads();

        float o[32][4];
        #pragma unroll
        for (int i = 0; i < 32; i++)
            #pragma unroll
            for (int j = 0; j < 4; j++) o[i][j] = 0.f;

        const int rA  = w * 16 + (l & 15);
        const int cA  = l >> 4;
        const int rxA = rA & 7;
        const int rWb = (l & 7) + ((l >> 3) & 1) * 8;
        const int cW  = l >> 4;
        const int rxW = l & 7;

        const __half* xg = gx + (size_t)m0 * DIN;
        proj_issue(sb, 0, 0, xg, W, tid);

        #pragma unroll 1
        for (int kb = 0; kb < 8; kb++) {
            const int st = kb & 1;
            if (kb + 1 < 8) {
                proj_issue(sb, st ^ 1, kb + 1, xg, W, tid);
                CP_WAIT1();
            } else {
                CP_WAIT0();
            }
            __syncthreads();

            const uint32_t sX = sb + st * PJ_XSTG;
            const uint32_t sW = sb + PJ_W0 + st * PJ_WSTG;

            #pragma unroll
            for (int ks = 0; ks < 4; ks++) {
                uint32_t a[4];
                ldsm4(sX + rA * 128 + (((2 * ks + cA) ^ rxA) << 4), a);
                #pragma unroll
                for (int g = 0; g < 16; g++) {
                    uint32_t bfr[4];
                    ldsm4t(sW + (ks * 16 + rWb) * 512 + (((2 * g + cW) ^ rxW) << 4), bfr);
                    mma_f16(o[2 * g],     a, bfr[0], bfr[1]);
                    mma_f16(o[2 * g + 1], a, bfr[2], bfr[3]);
                }
            }
            __syncthreads();
        }

        const int r0 = m0 + w * 16 + grp;
        #pragma unroll
        for (int nf = 0; nf < 32; nf++) {
            int col = nf * 8 + tid4 * 2;
            float b0 = bias[col], b1 = bias[col + 1];
            __half2 h0 = __floats2half2_rn((o[nf][0] + b0) * scl, (o[nf][1] + b1) * scl);
            __half2 h1 = __floats2half2_rn((o[nf][2] + b0) * scl, (o[nf][3] + b1) * scl);
            *(uint32_t*)(O + (size_t)r0 * DD + col)       = h2u(h0);
            *(uint32_t*)(O + (size_t)(r0 + 8) * DD + col) = h2u(h1);
        }
        __threadfence();
        __syncthreads();
        if (tid == 0) atomicAdd(&projDone[bb], 1);
        return;
    }

    // ==================== FLASH UNIT (one k-quarter of one q-tile) ====
    const int fid  = bid - (N_WU + N_XU + N_PU);
    const int kq   = fid >> 8;         // 0..3
    const int tile = fid & 255;
    const int b    = tile >> 5;
    const int q0   = (tile & 31) << 7;
    const size_t qbase = (size_t)b * SS + q0;
    const size_t kvb   = (size_t)b * SS;
    const int kt0 = kq * 16;           // 16 k-tiles of 64 keys each

    // wait for this batch's projection (producers all have lower bids)
    if (tid == 0) {
        spin_on(projDone + b, 96);
        __threadfence();
    }
    __syncthreads();

    // prologue: KV tile kt0 + Q tile in one cp.async group
    kv_issue_nc(sb, 0, gK + (kvb + kt0 * 64) * DD, gV + (kvb + kt0 * 64) * DD, tid);
    #pragma unroll
    for (int t = 0; t < 16; t++) {
        int idx = tid + t * 256;
        int r = idx >> 5, c = idx & 31;
        cpa16(sb + (uint32_t)(r * 512 + ((c ^ (r & 7)) << 4)),
              gQ + (qbase + r) * DD + c * 8);
    }
    CP_COMMIT();

    float o[32][4];
    #pragma unroll
    for (int i = 0; i < 32; i++)
        #pragma unroll
        for (int j = 0; j < 4; j++) o[i][j] = 0.f;
    float lsum0 = 0.f, lsum1 = 0.f;

    const int rA  = w * 16 + (l & 15);
    const int cA  = l >> 4;
    const int rxA = rA & 7;
    const uint32_t qrow = sb + rA * 512;
    const int rK  = ((l >> 4) << 3) + (l & 7);
    const int cK  = (l >> 3) & 1;
    const int rVb = (l & 7) + ((l >> 3) & 1) * 8;
    const int cV  = l >> 4;
    const int rx  = l & 7;

    #pragma unroll 1
    for (int kt = 0; kt < 16; kt++) {
        const int st = kt & 1;
        if (kt + 1 < 16) {
            kv_issue_nc(sb, st ^ 1, gK + (kvb + (kt0 + kt + 1) * 64) * DD,
                        gV + (kvb + (kt0 + kt + 1) * 64) * DD, tid);
            CP_COMMIT();
            CP_WAIT1();
        } else {
            CP_WAIT0();
        }
        __syncthreads();

        const uint32_t sKb = sb + FL_K0 + st * FL_STG;
        const uint32_t sVb = sb + FL_V0 + st * FL_STG;

        // ---- S = Q K^T  (16 rows x 64 keys per warp) ----
        float s[8][4];
        #pragma unroll
        for (int i = 0; i < 8; i++)
            #pragma unroll
            for (int j = 0; j < 4; j++) s[i][j] = 0.f;

        #pragma unroll
        for (int ks = 0; ks < 16; ks++) {
            uint32_t a[4];
            ldsm4(qrow + (((2 * ks + cA) ^ rxA) << 4), a);
            #pragma unroll
            for (int h = 0; h < 4; h++) {
                uint32_t kh[4];
                ldsm4(sKb + (rK + h * 16) * 512 + (((2 * ks + cK) ^ rx) << 4), kh);
                mma_f16(s[2 * h],     a, kh[0], kh[1]);
                mma_f16(s[2 * h + 1], a, kh[2], kh[3]);
            }
        }

        // ---- per-kb: softmax (exp2, pack) then PV for that kb ----
        // l summed from unquantized e (quantization noise of p averages out)
        #pragma unroll
        for (int kb = 0; kb < 4; kb++) {
            float e0 = ex2(s[2 * kb][0]),     e1 = ex2(s[2 * kb][1]);
            float e2 = ex2(s[2 * kb][2]),     e3 = ex2(s[2 * kb][3]);
            float e4 = ex2(s[2 * kb + 1][0]), e5 = ex2(s[2 * kb + 1][1]);
            float e6 = ex2(s[2 * kb + 1][2]), e7 = ex2(s[2 * kb + 1][3]);
            lsum0 += (e0 + e1) + (e4 + e5);
            lsum1 += (e2 + e3) + (e6 + e7);
            uint32_t pa[4];
            pa[0] = h2u(__floats2half2_rn(e0, e1));
            pa[1] = h2u(__floats2half2_rn(e2, e3));
            pa[2] = h2u(__floats2half2_rn(e4, e5));
            pa[3] = h2u(__floats2half2_rn(e6, e7));
            #pragma unroll
            for (int g = 0; g < 16; g++) {
                uint32_t v[4];
                ldsm4t(sVb + (rVb + kb * 16) * 512 + (((2 * g + cV) ^ rx) << 4), v);
                mma_f16(o[2 * g],     pa, v[0], v[1]);
                mma_f16(o[2 * g + 1], pa, v[2], v[3]);
            }
        }
        __syncthreads();
    }

    // quad-reduce l partials
    lsum0 += __shfl_xor_sync(0xffffffffu, lsum0, 1);
    lsum0 += __shfl_xor_sync(0xffffffffu, lsum0, 2);
    lsum1 += __shfl_xor_sync(0xffffffffu, lsum1, 1);
    lsum1 += __shfl_xor_sync(0xffffffffu, lsum1, 2);

    const int r0g = (int)(qbase + w * 16 + grp);   // global row of first row

    if (kq < 3) {
        // store O partial + l partial
        #pragma unroll
        for (int nf = 0; nf < 32; nf++) {
            int col = nf * 8 + tid4 * 2;
            size_t i0 = (size_t)r0g * DD + col;
            size_t i1 = (size_t)(r0g + 8) * DD + col;
            *(float2*)&gOp[kq][i0] = make_float2(o[nf][0], o[nf][1]);
            *(float2*)&gOp[kq][i1] = make_float2(o[nf][2], o[nf][3]);
        }
        if (tid4 == 0) {
            gLp[kq][r0g]     = lsum0;
            gLp[kq][r0g + 8] = lsum1;
        }
        __threadfence();
        __syncthreads();
        if (tid == 0) atomicAdd(&tileDone[tile], 1);
    } else {
        // final unit: wait for peers (all lower bids), merge, normalize, store
        if (tid == 0) {
            spin_on(tileDone + tile, 3);
            __threadfence();
        }
        __syncthreads();

        float l0 = lsum0 + gLp[0][r0g]     + gLp[1][r0g]     + gLp[2][r0g];
        float l1 = lsum1 + gLp[0][r0g + 8] + gLp[1][r0g + 8] + gLp[2][r0g + 8];
        const float inv0 = 1.f / l0, inv1 = 1.f / l1;

        #pragma unroll
        for (int nf = 0; nf < 32; nf++) {
            int col = nf * 8 + tid4 * 2;
            size_t i0 = (size_t)r0g * DD + col;
            size_t i1 = (size_t)(r0g + 8) * DD + col;
            float2 a = make_float2(o[nf][0], o[nf][1]);
            float2 c = make_float2(o[nf][2], o[nf][3]);
            #pragma unroll
            for (int k = 0; k < 3; k++) {
                float2 pa = *(const float2*)&gOp[k][i0];
                float2 pc = *(const float2*)&gOp[k][i1];
                a.x += pa.x; a.y += pa.y;
                c.x += pc.x; c.y += pc.y;
            }
            *(float2*)(out + i0) = make_float2(a.x * inv0, a.y * inv0);
            *(float2*)(out + i1) = make_float2(c.x * inv1, c.y * inv1);
        }
    }
}

// ---------------------------------------------------------------------------
extern "C" void kernel_launch(void* const* d_in, const int* in_sizes, int n_in,
                              void* d_out, int out_size)
{
    const float* x  = (const float*)d_in[0];
    const float* Wq = (const float*)d_in[1];
    const float* bq = (const float*)d_in[2];
    const float* Wk = (const float*)d_in[3];
    const float* bk = (const float*)d_in[4];
    const float* Wv = (const float*)d_in[5];
    const float* bv = (const float*)d_in[6];
    float* out = (float*)d_out;

    cudaFuncSetAttribute(mega, cudaFuncAttributeMaxDynamicSharedMemorySize,
                         MEGA_SMEM);

    zero_init<<<1, 256>>>();
    mega<<<GRID_MEGA, 256, MEGA_SMEM>>>(x, Wq, bq, Wk, bk, Wv, bv, out);
}

// round 13
// speedup vs baseline: 1.0208x; 1.0208x over previous
#include <cuda_runtime.h>
#include <cuda_fp16.h>
#include <cstdint>

#define BB   8
#define SS   4096
#define DIN  512
#define DD   256

// ---------------------------------------------------------------------------
// Global scratch (static __device__ arrays: no allocation)
// ---------------------------------------------------------------------------
__device__ __half gx[BB * SS * DIN];
__device__ __half gWq[DIN * DD], gWk[DIN * DD], gWv[DIN * DD];
__device__ __half gQ[BB * SS * DD], gK[BB * SS * DD], gV[BB * SS * DD];
__device__ float gOp[3][BB * SS * DD];   // O partials for k-quarters 0..2
__device__ float gLp[3][BB * SS];        // l partials
__device__ int   projDone[BB];           // per-batch proj completion counters
__device__ int   tileDone[256];          // per-qtile flash partial counters

// ---------------------------------------------------------------------------
// helpers
// ---------------------------------------------------------------------------
__device__ __forceinline__ uint32_t smem_u32(const void* p) {
    uint32_t a;
    asm("{ .reg .u64 t; cvta.to.shared.u64 t, %1; cvt.u32.u64 %0, t; }"
        : "=r"(a) : "l"(p));
    return a;
}
__device__ __forceinline__ void ldsm4(uint32_t a, uint32_t r[4]) {
    asm volatile("ldmatrix.sync.aligned.m8n8.x4.shared.b16 {%0,%1,%2,%3}, [%4];"
        : "=r"(r[0]), "=r"(r[1]), "=r"(r[2]), "=r"(r[3]) : "r"(a));
}
__device__ __forceinline__ void ldsm4t(uint32_t a, uint32_t r[4]) {
    asm volatile("ldmatrix.sync.aligned.m8n8.x4.trans.shared.b16 {%0,%1,%2,%3}, [%4];"
        : "=r"(r[0]), "=r"(r[1]), "=r"(r[2]), "=r"(r[3]) : "r"(a));
}
__device__ __forceinline__ void mma_f16(float c[4], const uint32_t a[4],
                                        uint32_t b0, uint32_t b1) {
    asm volatile(
        "mma.sync.aligned.m16n8k16.row.col.f32.f16.f16.f32 "
        "{%0,%1,%2,%3}, {%4,%5,%6,%7}, {%8,%9}, {%0,%1,%2,%3};"
        : "+f"(c[0]), "+f"(c[1]), "+f"(c[2]), "+f"(c[3])
        : "r"(a[0]), "r"(a[1]), "r"(a[2]), "r"(a[3]), "r"(b0), "r"(b1));
}
__device__ __forceinline__ float ex2(float x) {
    float r;
    asm("ex2.approx.f32 %0, %1;" : "=f"(r) : "f"(x));
    return r;
}
__device__ __forceinline__ uint32_t h2u(__half2 h) {
    return *reinterpret_cast<uint32_t*>(&h);
}
__device__ __forceinline__ void cpa16(uint32_t s, const void* g) {
    asm volatile("cp.async.cg.shared.global [%0], [%1], 16;" :: "r"(s), "l"(g));
}
#define CP_COMMIT() asm volatile("cp.async.commit_group;" ::: "memory")
#define CP_WAIT1()  asm volatile("cp.async.wait_group 1;" ::: "memory")
#define CP_WAIT0()  asm volatile("cp.async.wait_group 0;" ::: "memory")

__device__ __forceinline__ void spin_on(volatile int* ctr, int target) {
    while (*ctr < target) __nanosleep(128);
}

// ---------------------------------------------------------------------------
// Kernel 0: convert x + weights fp32->fp16, zero the flow counters.
// ---------------------------------------------------------------------------
#define NX4 (BB * SS * DIN / 4)
#define NW4 (DIN * DD / 4)

__global__ void convert_all(const float* __restrict__ x,
                            const float* __restrict__ Wq,
                            const float* __restrict__ Wk,
                            const float* __restrict__ Wv)
{
    if (blockIdx.x == 0) {
        int t = threadIdx.x;
        tileDone[t] = 0;
        if (t < BB) projDone[t] = 0;
    }
    int i = blockIdx.x * blockDim.x + threadIdx.x;
    const float* src;
    __half* dst;
    int idx;
    if (i < NX4) {
        src = x; dst = gx; idx = i;
    } else {
        int j = i - NX4;
        if (j >= 3 * NW4) return;
        int w = j / NW4;
        idx = j - w * NW4;
        src = (w == 0) ? Wq : (w == 1) ? Wk : Wv;
        dst = (w == 0) ? gWq : (w == 1) ? gWk : gWv;
    }
    float4 v = ((const float4*)src)[idx];
    __half2 a = __floats2half2_rn(v.x, v.y);
    __half2 b = __floats2half2_rn(v.z, v.w);
    ((uint2*)dst)[idx] = make_uint2(h2u(a), h2u(b));
}

// ---------------------------------------------------------------------------
// Fused mega-kernel. grid = 1792 CTAs, 256 thr, 192KB smem.
//   bid [0,768):      proj units, batch-major: b=bid/96, yb=(bid%96)/32, xt=bid%32
//   bid [768,1792):   flash units: fid=bid-768, kq=fid/256 (0..3), tile=fid%256
//                     tile -> b=tile/32, q0=(tile%32)*128; keys [kq*1024,(kq+1)*1024)
// Ordering guarantees every spinner waits only on lower-bid CTAs.
// ---------------------------------------------------------------------------
#define MEGA_SMEM 196608
// proj smem layout (within the 192KB)
#define PJ_W0     32768
#define PJ_XSTG   16384
#define PJ_WSTG   32768
// flash smem layout
#define FL_K0     65536
#define FL_V0     131072
#define FL_STG    32768

__device__ __forceinline__ void proj_issue(uint32_t sb, int st, int kb,
                                           const __half* xg, const __half* Wg,
                                           int tid)
{
    #pragma unroll
    for (int t = 0; t < 4; t++) {
        int idx = tid + t * 256;
        int r = idx >> 3, c = idx & 7;
        cpa16(sb + st * PJ_XSTG + (uint32_t)(r * 128 + ((c ^ (r & 7)) << 4)),
              xg + (size_t)r * DIN + kb * 64 + c * 8);
    }
    #pragma unroll
    for (int t = 0; t < 8; t++) {
        int idx = tid + t * 256;
        int r = idx >> 5, c = idx & 31;
        cpa16(sb + PJ_W0 + st * PJ_WSTG + (uint32_t)(r * 512 + ((c ^ (r & 7)) << 4)),
              Wg + (size_t)(kb * 64 + r) * DD + c * 8);
    }
    CP_COMMIT();
}

__device__ __forceinline__ void kv_issue_nc(uint32_t sb, int st,
                                            const __half* Kg, const __half* Vg,
                                            int tid)
{
    #pragma unroll
    for (int t = 0; t < 8; t++) {
        int idx = tid + t * 256;
        int r = idx >> 5, c = idx & 31;
        uint32_t off = (uint32_t)(r * 512 + ((c ^ (r & 7)) << 4));
        cpa16(sb + FL_K0 + st * FL_STG + off, Kg + (size_t)r * DD + c * 8);
        cpa16(sb + FL_V0 + st * FL_STG + off, Vg + (size_t)r * DD + c * 8);
    }
}

__global__ __launch_bounds__(256, 1) void mega(
    const float* __restrict__ bq, const float* __restrict__ bk,
    const float* __restrict__ bv, float* __restrict__ out)
{
    extern __shared__ char sm[];
    const uint32_t sb = smem_u32(sm);
    const int bid = blockIdx.x;
    const int tid = threadIdx.x;
    const int w   = tid >> 5;
    const int l   = tid & 31;
    const int grp = l >> 2, tid4 = l & 3;

    if (bid < 768) {
        // ==================== PROJ UNIT ====================
        const int bb = bid / 96;
        const int r96 = bid - bb * 96;
        const int yb = r96 >> 5;
        const int xt = r96 & 31;
        const int m0 = (bb * 32 + xt) * 128;

        const __half* W    = (yb == 0) ? gWq : (yb == 1) ? gWk : gWv;
        const float*  bias = (yb == 0) ? bq  : (yb == 1) ? bk  : bv;
        __half*       O    = (yb == 0) ? gQ  : (yb == 1) ? gK  : gV;
        const float scl = (yb == 0) ? 0.09014205f : 1.0f;  // log2(e)/16

        float o[32][4];
        #pragma unroll
        for (int i = 0; i < 32; i++)
            #pragma unroll
            for (int j = 0; j < 4; j++) o[i][j] = 0.f;

        const int rA  = w * 16 + (l & 15);
        const int cA  = l >> 4;
        const int rxA = rA & 7;
        const int rWb = (l & 7) + ((l >> 3) & 1) * 8;
        const int cW  = l >> 4;
        const int rxW = l & 7;

        const __half* xg = gx + (size_t)m0 * DIN;
        proj_issue(sb, 0, 0, xg, W, tid);

        #pragma unroll 1
        for (int kb = 0; kb < 8; kb++) {
            const int st = kb & 1;
            if (kb + 1 < 8) {
                proj_issue(sb, st ^ 1, kb + 1, xg, W, tid);
                CP_WAIT1();
            } else {
                CP_WAIT0();
            }
            __syncthreads();

            const uint32_t sX = sb + st * PJ_XSTG;
            const uint32_t sW = sb + PJ_W0 + st * PJ_WSTG;

            #pragma unroll
            for (int ks = 0; ks < 4; ks++) {
                uint32_t a[4];
                ldsm4(sX + rA * 128 + (((2 * ks + cA) ^ rxA) << 4), a);
                #pragma unroll
                for (int g = 0; g < 16; g++) {
                    uint32_t bfr[4];
                    ldsm4t(sW + (ks * 16 + rWb) * 512 + (((2 * g + cW) ^ rxW) << 4), bfr);
                    mma_f16(o[2 * g],     a, bfr[0], bfr[1]);
                    mma_f16(o[2 * g + 1], a, bfr[2], bfr[3]);
                }
            }
            __syncthreads();
        }

        const int r0 = m0 + w * 16 + grp;
        #pragma unroll
        for (int nf = 0; nf < 32; nf++) {
            int col = nf * 8 + tid4 * 2;
            float b0 = bias[col], b1 = bias[col + 1];
            __half2 h0 = __floats2half2_rn((o[nf][0] + b0) * scl, (o[nf][1] + b1) * scl);
            __half2 h1 = __floats2half2_rn((o[nf][2] + b0) * scl, (o[nf][3] + b1) * scl);
            *(uint32_t*)(O + (size_t)r0 * DD + col)       = h2u(h0);
            *(uint32_t*)(O + (size_t)(r0 + 8) * DD + col) = h2u(h1);
        }
        __threadfence();
        __syncthreads();
        if (tid == 0) atomicAdd(&projDone[bb], 1);
        return;
    }

    // ==================== FLASH UNIT (one k-quarter of one q-tile) ====
    const int fid  = bid - 768;
    const int kq   = fid >> 8;         // 0..3
    const int tile = fid & 255;
    const int b    = tile >> 5;
    const int q0   = (tile & 31) << 7;
    const size_t qbase = (size_t)b * SS + q0;
    const size_t kvb   = (size_t)b * SS;
    const int kt0 = kq * 16;           // 16 k-tiles of 64 keys each

    // wait for this batch's projection (producers all have lower bids)
    if (tid == 0) {
        spin_on(projDone + b, 96);
        __threadfence();
    }
    __syncthreads();

    // prologue: KV tile kt0 + Q tile in one cp.async group
    kv_issue_nc(sb, 0, gK + (kvb + kt0 * 64) * DD, gV + (kvb + kt0 * 64) * DD, tid);
    #pragma unroll
    for (int t = 0; t < 16; t++) {
        int idx = tid + t * 256;
        int r = idx >> 5, c = idx & 31;
        cpa16(sb + (uint32_t)(r * 512 + ((c ^ (r & 7)) << 4)),
              gQ + (qbase + r) * DD + c * 8);
    }
    CP_COMMIT();

    float o[32][4];
    #pragma unroll
    for (int i = 0; i < 32; i++)
        #pragma unroll
        for (int j = 0; j < 4; j++) o[i][j] = 0.f;
    float lsum0 = 0.f, lsum1 = 0.f;

    const int rA  = w * 16 + (l & 15);
    const int cA  = l >> 4;
    const int rxA = rA & 7;
    const uint32_t qrow = sb + rA * 512;
    const int rK  = ((l >> 4) << 3) + (l & 7);
    const int cK  = (l >> 3) & 1;
    const int rVb = (l & 7) + ((l >> 3) & 1) * 8;
    const int cV  = l >> 4;
    const int rx  = l & 7;

    #pragma unroll 1
    for (int kt = 0; kt < 16; kt++) {
        const int st = kt & 1;
        if (kt + 1 < 16) {
            kv_issue_nc(sb, st ^ 1, gK + (kvb + (kt0 + kt + 1) * 64) * DD,
                        gV + (kvb + (kt0 + kt + 1) * 64) * DD, tid);
            CP_COMMIT();
            CP_WAIT1();
        } else {
            CP_WAIT0();
        }
        __syncthreads();

        const uint32_t sKb = sb + FL_K0 + st * FL_STG;
        const uint32_t sVb = sb + FL_V0 + st * FL_STG;

        // ---- S = Q K^T  (16 rows x 64 keys per warp) ----
        float s[8][4];
        #pragma unroll
        for (int i = 0; i < 8; i++)
            #pragma unroll
            for (int j = 0; j < 4; j++) s[i][j] = 0.f;

        #pragma unroll
        for (int ks = 0; ks < 16; ks++) {
            uint32_t a[4];
            ldsm4(qrow + (((2 * ks + cA) ^ rxA) << 4), a);
            #pragma unroll
            for (int h = 0; h < 4; h++) {
                uint32_t kh[4];
                ldsm4(sKb + (rK + h * 16) * 512 + (((2 * ks + cK) ^ rx) << 4), kh);
                mma_f16(s[2 * h],     a, kh[0], kh[1]);
                mma_f16(s[2 * h + 1], a, kh[2], kh[3]);
            }
        }

        // ---- per-kb: softmax (exp2, pack) then PV for that kb ----
        // (shortens s/p live ranges; l summed from unquantized e)
        #pragma unroll
        for (int kb = 0; kb < 4; kb++) {
            float e0 = ex2(s[2 * kb][0]),     e1 = ex2(s[2 * kb][1]);
            float e2 = ex2(s[2 * kb][2]),     e3 = ex2(s[2 * kb][3]);
            float e4 = ex2(s[2 * kb + 1][0]), e5 = ex2(s[2 * kb + 1][1]);
            float e6 = ex2(s[2 * kb + 1][2]), e7 = ex2(s[2 * kb + 1][3]);
            lsum0 += (e0 + e1) + (e4 + e5);
            lsum1 += (e2 + e3) + (e6 + e7);
            uint32_t pa[4];
            pa[0] = h2u(__floats2half2_rn(e0, e1));
            pa[1] = h2u(__floats2half2_rn(e2, e3));
            pa[2] = h2u(__floats2half2_rn(e4, e5));
            pa[3] = h2u(__floats2half2_rn(e6, e7));
            #pragma unroll
            for (int g = 0; g < 16; g++) {
                uint32_t v[4];
                ldsm4t(sVb + (rVb + kb * 16) * 512 + (((2 * g + cV) ^ rx) << 4), v);
                mma_f16(o[2 * g],     pa, v[0], v[1]);
                mma_f16(o[2 * g + 1], pa, v[2], v[3]);
            }
        }
        __syncthreads();
    }

    // quad-reduce l partials
    lsum0 += __shfl_xor_sync(0xffffffffu, lsum0, 1);
    lsum0 += __shfl_xor_sync(0xffffffffu, lsum0, 2);
    lsum1 += __shfl_xor_sync(0xffffffffu, lsum1, 1);
    lsum1 += __shfl_xor_sync(0xffffffffu, lsum1, 2);

    const int r0g = (int)(qbase + w * 16 + grp);   // global row of first row

    if (kq < 3) {
        // store O partial + l partial
        #pragma unroll
        for (int nf = 0; nf < 32; nf++) {
            int col = nf * 8 + tid4 * 2;
            size_t i0 = (size_t)r0g * DD + col;
            size_t i1 = (size_t)(r0g + 8) * DD + col;
            *(float2*)&gOp[kq][i0] = make_float2(o[nf][0], o[nf][1]);
            *(float2*)&gOp[kq][i1] = make_float2(o[nf][2], o[nf][3]);
        }
        if (tid4 == 0) {
            gLp[kq][r0g]     = lsum0;
            gLp[kq][r0g + 8] = lsum1;
        }
        __threadfence();
        __syncthreads();
        if (tid == 0) atomicAdd(&tileDone[tile], 1);
    } else {
        // final unit: wait for peers (all lower bids), merge, normalize, store
        if (tid == 0) {
            spin_on(tileDone + tile, 3);
            __threadfence();
        }
        __syncthreads();

        float l0 = lsum0 + gLp[0][r0g]     + gLp[1][r0g]     + gLp[2][r0g];
        float l1 = lsum1 + gLp[0][r0g + 8] + gLp[1][r0g + 8] + gLp[2][r0g + 8];
        const float inv0 = 1.f / l0, inv1 = 1.f / l1;

        #pragma unroll
        for (int nf = 0; nf < 32; nf++) {
            int col = nf * 8 + tid4 * 2;
            size_t i0 = (size_t)r0g * DD + col;
            size_t i1 = (size_t)(r0g + 8) * DD + col;
            float2 a = make_float2(o[nf][0], o[nf][1]);
            float2 c = make_float2(o[nf][2], o[nf][3]);
            #pragma unroll
            for (int k = 0; k < 3; k++) {
                float2 pa = *(const float2*)&gOp[k][i0];
                float2 pc = *(const float2*)&gOp[k][i1];
                a.x += pa.x; a.y += pa.y;
                c.x += pc.x; c.y += pc.y;
            }
            *(float2*)(out + i0) = make_float2(a.x * inv0, a.y * inv0);
            *(float2*)(out + i1) = make_float2(c.x * inv1, c.y * inv1);
        }
    }
}

// ---------------------------------------------------------------------------
extern "C" void kernel_launch(void* const* d_in, const int* in_sizes, int n_in,
                              void* d_out, int out_size)
{
    const float* x  = (const float*)d_in[0];
    const float* Wq = (const float*)d_in[1];
    const float* bq = (const float*)d_in[2];
    const float* Wk = (const float*)d_in[3];
    const float* bk = (const float*)d_in[4];
    const float* Wv = (const float*)d_in[5];
    const float* bv = (const float*)d_in[6];
    float* out = (float*)d_out;

    cudaFuncSetAttribute(mega, cudaFuncAttributeMaxDynamicSharedMemorySize,
                         MEGA_SMEM);

    convert_all<<<(NX4 + 3 * NW4 + 255) / 256, 256>>>(x, Wq, Wk, Wv);
    mega<<<768 + 1024, 256, MEGA_SMEM>>>(bq, bk, bv, out);
}

// round 14
// speedup vs baseline: 1.0260x; 1.0051x over previous
#include <cuda_runtime.h>
#include <cuda_fp16.h>
#include <cstdint>

#define BB   8
#define SS   4096
#define DIN  512
#define DD   256

// ---------------------------------------------------------------------------
// Global scratch (static __device__ arrays: no allocation)
// ---------------------------------------------------------------------------
__device__ __half gx[BB * SS * DIN];
__device__ __half gWq[DIN * DD], gWk[DIN * DD], gWv[DIN * DD];
__device__ __half gQ[BB * SS * DD], gK[BB * SS * DD], gV[BB * SS * DD];
__device__ float gOp[3][BB * SS * DD];   // O partials for k-quarters 0..2
__device__ float gLp[3][BB * SS];        // l partials
__device__ int   projDone[BB];           // per-batch proj completion counters
__device__ int   tileDone[256];          // per-qtile flash partial counters

// ---------------------------------------------------------------------------
// helpers
// ---------------------------------------------------------------------------
__device__ __forceinline__ uint32_t smem_u32(const void* p) {
    uint32_t a;
    asm("{ .reg .u64 t; cvta.to.shared.u64 t, %1; cvt.u32.u64 %0, t; }"
        : "=r"(a) : "l"(p));
    return a;
}
__device__ __forceinline__ void ldsm4(uint32_t a, uint32_t r[4]) {
    asm volatile("ldmatrix.sync.aligned.m8n8.x4.shared.b16 {%0,%1,%2,%3}, [%4];"
        : "=r"(r[0]), "=r"(r[1]), "=r"(r[2]), "=r"(r[3]) : "r"(a));
}
__device__ __forceinline__ void ldsm4t(uint32_t a, uint32_t r[4]) {
    asm volatile("ldmatrix.sync.aligned.m8n8.x4.trans.shared.b16 {%0,%1,%2,%3}, [%4];"
        : "=r"(r[0]), "=r"(r[1]), "=r"(r[2]), "=r"(r[3]) : "r"(a));
}
__device__ __forceinline__ void mma_f16(float c[4], const uint32_t a[4],
                                        uint32_t b0, uint32_t b1) {
    asm volatile(
        "mma.sync.aligned.m16n8k16.row.col.f32.f16.f16.f32 "
        "{%0,%1,%2,%3}, {%4,%5,%6,%7}, {%8,%9}, {%0,%1,%2,%3};"
        : "+f"(c[0]), "+f"(c[1]), "+f"(c[2]), "+f"(c[3])
        : "r"(a[0]), "r"(a[1]), "r"(a[2]), "r"(a[3]), "r"(b0), "r"(b1));
}
__device__ __forceinline__ float ex2(float x) {
    float r;
    asm("ex2.approx.f32 %0, %1;" : "=f"(r) : "f"(x));
    return r;
}
__device__ __forceinline__ uint32_t h2u(__half2 h) {
    return *reinterpret_cast<uint32_t*>(&h);
}
__device__ __forceinline__ void cpa16(uint32_t s, const void* g) {
    asm volatile("cp.async.cg.shared.global [%0], [%1], 16;" :: "r"(s), "l"(g));
}
#define CP_COMMIT() asm volatile("cp.async.commit_group;" ::: "memory")
#define CP_WAIT1()  asm volatile("cp.async.wait_group 1;" ::: "memory")
#define CP_WAIT0()  asm volatile("cp.async.wait_group 0;" ::: "memory")

__device__ __forceinline__ void spin_on(volatile int* ctr, int target) {
    while (*ctr < target) __nanosleep(128);
}

__device__ __forceinline__ uint2 cvt_f4(float4 v) {
    __half2 a = __floats2half2_rn(v.x, v.y);
    __half2 b = __floats2half2_rn(v.z, v.w);
    return make_uint2(h2u(a), h2u(b));
}

// ---------------------------------------------------------------------------
// Kernel 0: convert x + weights fp32->fp16, zero the flow counters.
// MLP-4 grid-stride for the x bulk (1024 CTAs x 4 iters, exact tiling);
// 96 trailing CTAs (32 per weight) handle W stride-coalesced.
// ---------------------------------------------------------------------------
#define NX4 (BB * SS * DIN / 4)     // 4194304 float4
#define NW4 (DIN * DD / 4)          // 32768 float4 per weight
#define CV_XB 1024                  // x CTAs
#define CV_WB 96                    // W CTAs (32 per weight)
#define CV_GRID (CV_XB + CV_WB)

__global__ void convert_all(const float* __restrict__ x,
                            const float* __restrict__ Wq,
                            const float* __restrict__ Wk,
                            const float* __restrict__ Wv)
{
    if (blockIdx.x == 0) {
        int t = threadIdx.x;
        tileDone[t] = 0;
        if (t < BB) projDone[t] = 0;
    }

    if (blockIdx.x < CV_XB) {
        // x bulk: 4 independent loads in flight per iteration
        const int s  = CV_XB * 256;                   // 262144
        const int i0 = blockIdx.x * 256 + threadIdx.x;
        const float4* xi = (const float4*)x;
        uint2* xo = (uint2*)gx;
        #pragma unroll 1
        for (int i = i0; i < NX4; i += 4 * s) {       // 4 exact iterations
            float4 v0 = xi[i];
            float4 v1 = xi[i + s];
            float4 v2 = xi[i + 2 * s];
            float4 v3 = xi[i + 3 * s];
            xo[i]         = cvt_f4(v0);
            xo[i + s]     = cvt_f4(v1);
            xo[i + 2 * s] = cvt_f4(v2);
            xo[i + 3 * s] = cvt_f4(v3);
        }
    } else {
        // weights: 32 blocks per W, 1024 f4 per block, 4 per thread
        const int u  = blockIdx.x - CV_XB;
        const int wi = u >> 5;                        // 0..2
        const int base = (u & 31) * 1024;
        const float4* src = (wi == 0) ? (const float4*)Wq
                          : (wi == 1) ? (const float4*)Wk : (const float4*)Wv;
        uint2* dst = (uint2*)((wi == 0) ? gWq : (wi == 1) ? gWk : gWv);
        const int i0 = base + threadIdx.x;
        float4 v0 = src[i0];
        float4 v1 = src[i0 + 256];
        float4 v2 = src[i0 + 512];
        float4 v3 = src[i0 + 768];
        dst[i0]       = cvt_f4(v0);
        dst[i0 + 256] = cvt_f4(v1);
        dst[i0 + 512] = cvt_f4(v2);
        dst[i0 + 768] = cvt_f4(v3);
    }
}

// ---------------------------------------------------------------------------
// Fused mega-kernel. grid = 1792 CTAs, 256 thr, 192KB smem.
//   bid [0,768):      proj units, batch-major: b=bid/96, yb=(bid%96)/32, xt=bid%32
//   bid [768,1792):   flash units: fid=bid-768, kq=fid/256 (0..3), tile=fid%256
//                     tile -> b=tile/32, q0=(tile%32)*128; keys [kq*1024,(kq+1)*1024)
// Ordering guarantees every spinner waits only on lower-bid CTAs.
// ---------------------------------------------------------------------------
#define MEGA_SMEM 196608
// proj smem layout (within the 192KB)
#define PJ_W0     32768
#define PJ_XSTG   16384
#define PJ_WSTG   32768
// flash smem layout
#define FL_K0     65536
#define FL_V0     131072
#define FL_STG    32768

__device__ __forceinline__ void proj_issue(uint32_t sb, int st, int kb,
                                           const __half* xg, const __half* Wg,
                                           int tid)
{
    #pragma unroll
    for (int t = 0; t < 4; t++) {
        int idx = tid + t * 256;
        int r = idx >> 3, c = idx & 7;
        cpa16(sb + st * PJ_XSTG + (uint32_t)(r * 128 + ((c ^ (r & 7)) << 4)),
              xg + (size_t)r * DIN + kb * 64 + c * 8);
    }
    #pragma unroll
    for (int t = 0; t < 8; t++) {
        int idx = tid + t * 256;
        int r = idx >> 5, c = idx & 31;
        cpa16(sb + PJ_W0 + st * PJ_WSTG + (uint32_t)(r * 512 + ((c ^ (r & 7)) << 4)),
              Wg + (size_t)(kb * 64 + r) * DD + c * 8);
    }
    CP_COMMIT();
}

__device__ __forceinline__ void kv_issue_nc(uint32_t sb, int st,
                                            const __half* Kg, const __half* Vg,
                                            int tid)
{
    #pragma unroll
    for (int t = 0; t < 8; t++) {
        int idx = tid + t * 256;
        int r = idx >> 5, c = idx & 31;
        uint32_t off = (uint32_t)(r * 512 + ((c ^ (r & 7)) << 4));
        cpa16(sb + FL_K0 + st * FL_STG + off, Kg + (size_t)r * DD + c * 8);
        cpa16(sb + FL_V0 + st * FL_STG + off, Vg + (size_t)r * DD + c * 8);
    }
}

__global__ __launch_bounds__(256, 1) void mega(
    const float* __restrict__ bq, const float* __restrict__ bk,
    const float* __restrict__ bv, float* __restrict__ out)
{
    extern __shared__ char sm[];
    const uint32_t sb = smem_u32(sm);
    const int bid = blockIdx.x;
    const int tid = threadIdx.x;
    const int w   = tid >> 5;
    const int l   = tid & 31;
    const int grp = l >> 2, tid4 = l & 3;

    if (bid < 768) {
        // ==================== PROJ UNIT ====================
        const int bb = bid / 96;
        const int r96 = bid - bb * 96;
        const int yb = r96 >> 5;
        const int xt = r96 & 31;
        const int m0 = (bb * 32 + xt) * 128;

        const __half* W    = (yb == 0) ? gWq : (yb == 1) ? gWk : gWv;
        const float*  bias = (yb == 0) ? bq  : (yb == 1) ? bk  : bv;
        __half*       O    = (yb == 0) ? gQ  : (yb == 1) ? gK  : gV;
        const float scl = (yb == 0) ? 0.09014205f : 1.0f;  // log2(e)/16

        float o[32][4];
        #pragma unroll
        for (int i = 0; i < 32; i++)
            #pragma unroll
            for (int j = 0; j < 4; j++) o[i][j] = 0.f;

        const int rA  = w * 16 + (l & 15);
        const int cA  = l >> 4;
        const int rxA = rA & 7;
        const int rWb = (l & 7) + ((l >> 3) & 1) * 8;
        const int cW  = l >> 4;
        const int rxW = l & 7;

        const __half* xg = gx + (size_t)m0 * DIN;
        proj_issue(sb, 0, 0, xg, W, tid);

        #pragma unroll 1
        for (int kb = 0; kb < 8; kb++) {
            const int st = kb & 1;
            if (kb + 1 < 8) {
                proj_issue(sb, st ^ 1, kb + 1, xg, W, tid);
                CP_WAIT1();
            } else {
                CP_WAIT0();
            }
            __syncthreads();

            const uint32_t sX = sb + st * PJ_XSTG;
            const uint32_t sW = sb + PJ_W0 + st * PJ_WSTG;

            #pragma unroll
            for (int ks = 0; ks < 4; ks++) {
                uint32_t a[4];
                ldsm4(sX + rA * 128 + (((2 * ks + cA) ^ rxA) << 4), a);
                #pragma unroll
                for (int g = 0; g < 16; g++) {
                    uint32_t bfr[4];
                    ldsm4t(sW + (ks * 16 + rWb) * 512 + (((2 * g + cW) ^ rxW) << 4), bfr);
                    mma_f16(o[2 * g],     a, bfr[0], bfr[1]);
                    mma_f16(o[2 * g + 1], a, bfr[2], bfr[3]);
                }
            }
            __syncthreads();
        }

        const int r0 = m0 + w * 16 + grp;
        #pragma unroll
        for (int nf = 0; nf < 32; nf++) {
            int col = nf * 8 + tid4 * 2;
            float b0 = bias[col], b1 = bias[col + 1];
            __half2 h0 = __floats2half2_rn((o[nf][0] + b0) * scl, (o[nf][1] + b1) * scl);
            __half2 h1 = __floats2half2_rn((o[nf][2] + b0) * scl, (o[nf][3] + b1) * scl);
            *(uint32_t*)(O + (size_t)r0 * DD + col)       = h2u(h0);
            *(uint32_t*)(O + (size_t)(r0 + 8) * DD + col) = h2u(h1);
        }
        __threadfence();
        __syncthreads();
        if (tid == 0) atomicAdd(&projDone[bb], 1);
        return;
    }

    // ==================== FLASH UNIT (one k-quarter of one q-tile) ====
    const int fid  = bid - 768;
    const int kq   = fid >> 8;         // 0..3
    const int tile = fid & 255;
    const int b    = tile >> 5;
    const int q0   = (tile & 31) << 7;
    const size_t qbase = (size_t)b * SS + q0;
    const size_t kvb   = (size_t)b * SS;
    const int kt0 = kq * 16;           // 16 k-tiles of 64 keys each

    // wait for this batch's projection (producers all have lower bids)
    if (tid == 0) {
        spin_on(projDone + b, 96);
        __threadfence();
    }
    __syncthreads();

    // prologue: KV tile kt0 + Q tile in one cp.async group
    kv_issue_nc(sb, 0, gK + (kvb + kt0 * 64) * DD, gV + (kvb + kt0 * 64) * DD, tid);
    #pragma unroll
    for (int t = 0; t < 16; t++) {
        int idx = tid + t * 256;
        int r = idx >> 5, c = idx & 31;
        cpa16(sb + (uint32_t)(r * 512 + ((c ^ (r & 7)) << 4)),
              gQ + (qbase + r) * DD + c * 8);
    }
    CP_COMMIT();

    float o[32][4];
    #pragma unroll
    for (int i = 0; i < 32; i++)
        #pragma unroll
        for (int j = 0; j < 4; j++) o[i][j] = 0.f;
    float lsum0 = 0.f, lsum1 = 0.f;

    const int rA  = w * 16 + (l & 15);
    const int cA  = l >> 4;
    const int rxA = rA & 7;
    const uint32_t qrow = sb + rA * 512;
    const int rK  = ((l >> 4) << 3) + (l & 7);
    const int cK  = (l >> 3) & 1;
    const int rVb = (l & 7) + ((l >> 3) & 1) * 8;
    const int cV  = l >> 4;
    const int rx  = l & 7;

    #pragma unroll 1
    for (int kt = 0; kt < 16; kt++) {
        const int st = kt & 1;
        if (kt + 1 < 16) {
            kv_issue_nc(sb, st ^ 1, gK + (kvb + (kt0 + kt + 1) * 64) * DD,
                        gV + (kvb + (kt0 + kt + 1) * 64) * DD, tid);
            CP_COMMIT();
            CP_WAIT1();
        } else {
            CP_WAIT0();
        }
        __syncthreads();

        const uint32_t sKb = sb + FL_K0 + st * FL_STG;
        const uint32_t sVb = sb + FL_V0 + st * FL_STG;

        // ---- S = Q K^T  (16 rows x 64 keys per warp) ----
        float s[8][4];
        #pragma unroll
        for (int i = 0; i < 8; i++)
            #pragma unroll
            for (int j = 0; j < 4; j++) s[i][j] = 0.f;

        #pragma unroll
        for (int ks = 0; ks < 16; ks++) {
            uint32_t a[4];
            ldsm4(qrow + (((2 * ks + cA) ^ rxA) << 4), a);
            #pragma unroll
            for (int h = 0; h < 4; h++) {
                uint32_t kh[4];
                ldsm4(sKb + (rK + h * 16) * 512 + (((2 * ks + cK) ^ rx) << 4), kh);
                mma_f16(s[2 * h],     a, kh[0], kh[1]);
                mma_f16(s[2 * h + 1], a, kh[2], kh[3]);
            }
        }

        // ---- per-kb: softmax (exp2, pack) then PV for that kb ----
        // (shortens s/p live ranges; l summed from unquantized e)
        #pragma unroll
        for (int kb = 0; kb < 4; kb++) {
            float e0 = ex2(s[2 * kb][0]),     e1 = ex2(s[2 * kb][1]);
            float e2 = ex2(s[2 * kb][2]),     e3 = ex2(s[2 * kb][3]);
            float e4 = ex2(s[2 * kb + 1][0]), e5 = ex2(s[2 * kb + 1][1]);
            float e6 = ex2(s[2 * kb + 1][2]), e7 = ex2(s[2 * kb + 1][3]);
            lsum0 += (e0 + e1) + (e4 + e5);
            lsum1 += (e2 + e3) + (e6 + e7);
            uint32_t pa[4];
            pa[0] = h2u(__floats2half2_rn(e0, e1));
            pa[1] = h2u(__floats2half2_rn(e2, e3));
            pa[2] = h2u(__floats2half2_rn(e4, e5));
            pa[3] = h2u(__floats2half2_rn(e6, e7));
            #pragma unroll
            for (int g = 0; g < 16; g++) {
                uint32_t v[4];
                ldsm4t(sVb + (rVb + kb * 16) * 512 + (((2 * g + cV) ^ rx) << 4), v);
                mma_f16(o[2 * g],     pa, v[0], v[1]);
                mma_f16(o[2 * g + 1], pa, v[2], v[3]);
            }
        }
        __syncthreads();
    }

    // quad-reduce l partials
    lsum0 += __shfl_xor_sync(0xffffffffu, lsum0, 1);
    lsum0 += __shfl_xor_sync(0xffffffffu, lsum0, 2);
    lsum1 += __shfl_xor_sync(0xffffffffu, lsum1, 1);
    lsum1 += __shfl_xor_sync(0xffffffffu, lsum1, 2);

    const int r0g = (int)(qbase + w * 16 + grp);   // global row of first row

    if (kq < 3) {
        // store O partial + l partial
        #pragma unroll
        for (int nf = 0; nf < 32; nf++) {
            int col = nf * 8 + tid4 * 2;
            size_t i0 = (size_t)r0g * DD + col;
            size_t i1 = (size_t)(r0g + 8) * DD + col;
            *(float2*)&gOp[kq][i0] = make_float2(o[nf][0], o[nf][1]);
            *(float2*)&gOp[kq][i1] = make_float2(o[nf][2], o[nf][3]);
        }
        if (tid4 == 0) {
            gLp[kq][r0g]     = lsum0;
            gLp[kq][r0g + 8] = lsum1;
        }
        __threadfence();
        __syncthreads();
        if (tid == 0) atomicAdd(&tileDone[tile], 1);
    } else {
        // final unit: wait for peers (all lower bids), merge, normalize, store
        if (tid == 0) {
            spin_on(tileDone + tile, 3);
            __threadfence();
        }
        __syncthreads();

        float l0 = lsum0 + gLp[0][r0g]     + gLp[1][r0g]     + gLp[2][r0g];
        float l1 = lsum1 + gLp[0][r0g + 8] + gLp[1][r0g + 8] + gLp[2][r0g + 8];
        const float inv0 = 1.f / l0, inv1 = 1.f / l1;

        #pragma unroll
        for (int nf = 0; nf < 32; nf++) {
            int col = nf * 8 + tid4 * 2;
            size_t i0 = (size_t)r0g * DD + col;
            size_t i1 = (size_t)(r0g + 8) * DD + col;
            float2 a = make_float2(o[nf][0], o[nf][1]);
            float2 c = make_float2(o[nf][2], o[nf][3]);
            #pragma unroll
            for (int k = 0; k < 3; k++) {
                float2 pa = *(const float2*)&gOp[k][i0];
                float2 pc = *(const float2*)&gOp[k][i1];
                a.x += pa.x; a.y += pa.y;
                c.x += pc.x; c.y += pc.y;
            }
            *(float2*)(out + i0) = make_float2(a.x * inv0, a.y * inv0);
            *(float2*)(out + i1) = make_float2(c.x * inv1, c.y * inv1);
        }
    }
}

// ---------------------------------------------------------------------------
extern "C" void kernel_launch(void* const* d_in, const int* in_sizes, int n_in,
                              void* d_out, int out_size)
{
    const float* x  = (const float*)d_in[0];
    const float* Wq = (const float*)d_in[1];
    const float* bq = (const float*)d_in[2];
    const float* Wk = (const float*)d_in[3];
    const float* bk = (const float*)d_in[4];
    const float* Wv = (const float*)d_in[5];
    const float* bv = (const float*)d_in[6];
    float* out = (float*)d_out;

    cudaFuncSetAttribute(mega, cudaFuncAttributeMaxDynamicSharedMemorySize,
                         MEGA_SMEM);

    convert_all<<<CV_GRID, 256>>>(x, Wq, Wk, Wv);
    mega<<<768 + 1024, 256, MEGA_SMEM>>>(bq, bk, bv, out);
}

// round 15
// speedup vs baseline: 1.0337x; 1.0075x over previous
#include <cuda_runtime.h>
#include <cuda_fp16.h>
#include <cstdint>

#define BB   8
#define SS   4096
#define DIN  512
#define DD   256

// ---------------------------------------------------------------------------
// Global scratch (static __device__ arrays: no allocation)
// ---------------------------------------------------------------------------
__device__ __half gx[BB * SS * DIN];
__device__ __half gWq[DIN * DD], gWk[DIN * DD], gWv[DIN * DD];
__device__ __half gQ[BB * SS * DD], gK[BB * SS * DD], gV[BB * SS * DD];
__device__ float gOp[3][BB * SS * DD];   // O partials for k-quarters 0..2
__device__ float gLp[3][BB * SS];        // l partials
__device__ int   projDone[BB];           // per-batch proj completion counters
__device__ int   tileDone[256];          // per-qtile flash partial counters

// ---------------------------------------------------------------------------
// helpers
// ---------------------------------------------------------------------------
__device__ __forceinline__ uint32_t smem_u32(const void* p) {
    uint32_t a;
    asm("{ .reg .u64 t; cvta.to.shared.u64 t, %1; cvt.u32.u64 %0, t; }"
        : "=r"(a) : "l"(p));
    return a;
}
__device__ __forceinline__ void ldsm4(uint32_t a, uint32_t r[4]) {
    asm volatile("ldmatrix.sync.aligned.m8n8.x4.shared.b16 {%0,%1,%2,%3}, [%4];"
        : "=r"(r[0]), "=r"(r[1]), "=r"(r[2]), "=r"(r[3]) : "r"(a));
}
__device__ __forceinline__ void ldsm4t(uint32_t a, uint32_t r[4]) {
    asm volatile("ldmatrix.sync.aligned.m8n8.x4.trans.shared.b16 {%0,%1,%2,%3}, [%4];"
        : "=r"(r[0]), "=r"(r[1]), "=r"(r[2]), "=r"(r[3]) : "r"(a));
}
__device__ __forceinline__ void mma_f16(float c[4], const uint32_t a[4],
                                        uint32_t b0, uint32_t b1) {
    asm volatile(
        "mma.sync.aligned.m16n8k16.row.col.f32.f16.f16.f32 "
        "{%0,%1,%2,%3}, {%4,%5,%6,%7}, {%8,%9}, {%0,%1,%2,%3};"
        : "+f"(c[0]), "+f"(c[1]), "+f"(c[2]), "+f"(c[3])
        : "r"(a[0]), "r"(a[1]), "r"(a[2]), "r"(a[3]), "r"(b0), "r"(b1));
}
__device__ __forceinline__ float ex2(float x) {
    float r;
    asm("ex2.approx.f32 %0, %1;" : "=f"(r) : "f"(x));
    return r;
}
__device__ __forceinline__ uint32_t h2u(__half2 h) {
    return *reinterpret_cast<uint32_t*>(&h);
}
__device__ __forceinline__ void cpa16(uint32_t s, const void* g) {
    asm volatile("cp.async.cg.shared.global [%0], [%1], 16;" :: "r"(s), "l"(g));
}
#define CP_COMMIT() asm volatile("cp.async.commit_group;" ::: "memory")
#define CP_WAIT1()  asm volatile("cp.async.wait_group 1;" ::: "memory")
#define CP_WAIT0()  asm volatile("cp.async.wait_group 0;" ::: "memory")

__device__ __forceinline__ void spin_on(volatile int* ctr, int target) {
    while (*ctr < target) __nanosleep(128);
}

__device__ __forceinline__ uint2 cvt_f4(float4 v) {
    __half2 a = __floats2half2_rn(v.x, v.y);
    __half2 b = __floats2half2_rn(v.z, v.w);
    return make_uint2(h2u(a), h2u(b));
}

// ---------------------------------------------------------------------------
// Kernel 0: convert x + weights fp32->fp16, zero the flow counters.
// MLP-4 grid-stride for the x bulk (1024 CTAs x 4 iters, exact tiling);
// 96 trailing CTAs (32 per weight) handle W stride-coalesced.
// ---------------------------------------------------------------------------
#define NX4 (BB * SS * DIN / 4)     // 4194304 float4
#define NW4 (DIN * DD / 4)          // 32768 float4 per weight
#define CV_XB 1024                  // x CTAs
#define CV_WB 96                    // W CTAs (32 per weight)
#define CV_GRID (CV_XB + CV_WB)

__global__ void convert_all(const float* __restrict__ x,
                            const float* __restrict__ Wq,
                            const float* __restrict__ Wk,
                            const float* __restrict__ Wv)
{
    if (blockIdx.x == 0) {
        int t = threadIdx.x;
        tileDone[t] = 0;
        if (t < BB) projDone[t] = 0;
    }

    if (blockIdx.x < CV_XB) {
        // x bulk: 4 independent loads in flight per iteration
        const int s  = CV_XB * 256;                   // 262144
        const int i0 = blockIdx.x * 256 + threadIdx.x;
        const float4* xi = (const float4*)x;
        uint2* xo = (uint2*)gx;
        #pragma unroll 1
        for (int i = i0; i < NX4; i += 4 * s) {       // 4 exact iterations
            float4 v0 = xi[i];
            float4 v1 = xi[i + s];
            float4 v2 = xi[i + 2 * s];
            float4 v3 = xi[i + 3 * s];
            xo[i]         = cvt_f4(v0);
            xo[i + s]     = cvt_f4(v1);
            xo[i + 2 * s] = cvt_f4(v2);
            xo[i + 3 * s] = cvt_f4(v3);
        }
    } else {
        // weights: 32 blocks per W, 1024 f4 per block, 4 per thread
        const int u  = blockIdx.x - CV_XB;
        const int wi = u >> 5;                        // 0..2
        const int base = (u & 31) * 1024;
        const float4* src = (wi == 0) ? (const float4*)Wq
                          : (wi == 1) ? (const float4*)Wk : (const float4*)Wv;
        uint2* dst = (uint2*)((wi == 0) ? gWq : (wi == 1) ? gWk : gWv);
        const int i0 = base + threadIdx.x;
        float4 v0 = src[i0];
        float4 v1 = src[i0 + 256];
        float4 v2 = src[i0 + 512];
        float4 v3 = src[i0 + 768];
        dst[i0]       = cvt_f4(v0);
        dst[i0 + 256] = cvt_f4(v1);
        dst[i0 + 512] = cvt_f4(v2);
        dst[i0 + 768] = cvt_f4(v3);
    }
}

// ---------------------------------------------------------------------------
// Fused mega-kernel. grid = 1792 CTAs, 256 thr, 192KB smem.
//   bid [0,768):      proj units, batch-major: b=bid/96, yb=(bid%96)/32, xt=bid%32
//   bid [768,1792):   flash units: fid=bid-768, kq=fid/256 (0..3), tile=fid%256
//                     tile -> b=tile/32, q0=(tile%32)*128; keys [kq*1024,(kq+1)*1024)
// Ordering guarantees every spinner waits only on lower-bid CTAs.
// PROJ warp tiling: 4x2 grid, warp = 32 rows x 128 cols (B-frag dedup 8x->4x:
//   per ks 2 A-ldsm + 8 B-ldsm feed 32 mma; 320 ldsm/warp vs 544 before).
// Accumulation order per output element unchanged -> Q/K/V bit-identical.
// ---------------------------------------------------------------------------
#define MEGA_SMEM 196608
// proj smem layout (within the 192KB)
#define PJ_W0     32768
#define PJ_XSTG   16384
#define PJ_WSTG   32768
// flash smem layout
#define FL_K0     65536
#define FL_V0     131072
#define FL_STG    32768

__device__ __forceinline__ void proj_issue(uint32_t sb, int st, int kb,
                                           const __half* xg, const __half* Wg,
                                           int tid)
{
    #pragma unroll
    for (int t = 0; t < 4; t++) {
        int idx = tid + t * 256;
        int r = idx >> 3, c = idx & 7;
        cpa16(sb + st * PJ_XSTG + (uint32_t)(r * 128 + ((c ^ (r & 7)) << 4)),
              xg + (size_t)r * DIN + kb * 64 + c * 8);
    }
    #pragma unroll
    for (int t = 0; t < 8; t++) {
        int idx = tid + t * 256;
        int r = idx >> 5, c = idx & 31;
        cpa16(sb + PJ_W0 + st * PJ_WSTG + (uint32_t)(r * 512 + ((c ^ (r & 7)) << 4)),
              Wg + (size_t)(kb * 64 + r) * DD + c * 8);
    }
    CP_COMMIT();
}

__device__ __forceinline__ void kv_issue_nc(uint32_t sb, int st,
                                            const __half* Kg, const __half* Vg,
                                            int tid)
{
    #pragma unroll
    for (int t = 0; t < 8; t++) {
        int idx = tid + t * 256;
        int r = idx >> 5, c = idx & 31;
        uint32_t off = (uint32_t)(r * 512 + ((c ^ (r & 7)) << 4));
        cpa16(sb + FL_K0 + st * FL_STG + off, Kg + (size_t)r * DD + c * 8);
        cpa16(sb + FL_V0 + st * FL_STG + off, Vg + (size_t)r * DD + c * 8);
    }
}

__global__ __launch_bounds__(256, 1) void mega(
    const float* __restrict__ bq, const float* __restrict__ bk,
    const float* __restrict__ bv, float* __restrict__ out)
{
    extern __shared__ char sm[];
    const uint32_t sb = smem_u32(sm);
    const int bid = blockIdx.x;
    const int tid = threadIdx.x;
    const int w   = tid >> 5;
    const int l   = tid & 31;
    const int grp = l >> 2, tid4 = l & 3;

    if (bid < 768) {
        // ==================== PROJ UNIT (32x128 warp tile, 4x2 grid) =====
        const int bb = bid / 96;
        const int r96 = bid - bb * 96;
        const int yb = r96 >> 5;
        const int xt = r96 & 31;
        const int m0 = (bb * 32 + xt) * 128;

        const __half* W    = (yb == 0) ? gWq : (yb == 1) ? gWk : gWv;
        const float*  bias = (yb == 0) ? bq  : (yb == 1) ? bk  : bv;
        __half*       O    = (yb == 0) ? gQ  : (yb == 1) ? gK  : gV;
        const float scl = (yb == 0) ? 0.09014205f : 1.0f;  // log2(e)/16

        float o[32][4];   // [i*16+j]: rows 32mq+16i+grp(+8), cols 128nh+8j+tid4*2
        #pragma unroll
        for (int i = 0; i < 32; i++)
            #pragma unroll
            for (int j = 0; j < 4; j++) o[i][j] = 0.f;

        const int mq = w & 3;          // row quarter (32 rows)
        const int nh = w >> 2;         // col half (128 cols)
        const int rQ = l & 15;
        const int cQ = l >> 4;
        const int rxQ = rQ & 7;        // (32mq + rQ) & 7 == rQ & 7
        const int rWb = (l & 7) + ((l >> 3) & 1) * 8;
        const int cW  = l >> 4;
        const int rxW = l & 7;

        const __half* xg = gx + (size_t)m0 * DIN;
        proj_issue(sb, 0, 0, xg, W, tid);

        #pragma unroll 1
        for (int kb = 0; kb < 8; kb++) {
            const int st = kb & 1;
            if (kb + 1 < 8) {
                proj_issue(sb, st ^ 1, kb + 1, xg, W, tid);
                CP_WAIT1();
            } else {
                CP_WAIT0();
            }
            __syncthreads();

            const uint32_t sX = sb + st * PJ_XSTG;
            const uint32_t sW = sb + PJ_W0 + st * PJ_WSTG;
            const uint32_t xrow0 = sX + (32 * mq + rQ) * 128;
            const uint32_t xrow1 = sX + (32 * mq + 16 + rQ) * 128;

            #pragma unroll
            for (int ks = 0; ks < 4; ks++) {
                uint32_t a0[4], a1[4];
                ldsm4(xrow0 + (((2 * ks + cQ) ^ rxQ) << 4), a0);
                ldsm4(xrow1 + (((2 * ks + cQ) ^ rxQ) << 4), a1);
                #pragma unroll
                for (int j = 0; j < 8; j++) {
                    uint32_t bfr[4];
                    ldsm4t(sW + (ks * 16 + rWb) * 512
                              + (((16 * nh + 2 * j + cW) ^ rxW) << 4), bfr);
                    mma_f16(o[2 * j],          a0, bfr[0], bfr[1]);
                    mma_f16(o[2 * j + 1],      a0, bfr[2], bfr[3]);
                    mma_f16(o[16 + 2 * j],     a1, bfr[0], bfr[1]);
                    mma_f16(o[16 + 2 * j + 1], a1, bfr[2], bfr[3]);
                }
            }
            __syncthreads();
        }

        // epilogue: bias + scale + fp16 store (rows 32mq+16i+grp(+8))
        #pragma unroll
        for (int i = 0; i < 2; i++) {
            const int r0 = m0 + 32 * mq + 16 * i + grp;
            #pragma unroll
            for (int j = 0; j < 16; j++) {
                int col = 128 * nh + 8 * j + tid4 * 2;
                float b0 = bias[col], b1 = bias[col + 1];
                float* oc = o[i * 16 + j];
                __half2 h0 = __floats2half2_rn((oc[0] + b0) * scl, (oc[1] + b1) * scl);
                __half2 h1 = __floats2half2_rn((oc[2] + b0) * scl, (oc[3] + b1) * scl);
                *(uint32_t*)(O + (size_t)r0 * DD + col)       = h2u(h0);
                *(uint32_t*)(O + (size_t)(r0 + 8) * DD + col) = h2u(h1);
            }
        }
        __threadfence();
        __syncthreads();
        if (tid == 0) atomicAdd(&projDone[bb], 1);
        return;
    }

    // ==================== FLASH UNIT (one k-quarter of one q-tile) ====
    const int fid  = bid - 768;
    const int kq   = fid >> 8;         // 0..3
    const int tile = fid & 255;
    const int b    = tile >> 5;
    const int q0   = (tile & 31) << 7;
    const size_t qbase = (size_t)b * SS + q0;
    const size_t kvb   = (size_t)b * SS;
    const int kt0 = kq * 16;           // 16 k-tiles of 64 keys each

    // wait for this batch's projection (producers all have lower bids)
    if (tid == 0) {
        spin_on(projDone + b, 96);
        __threadfence();
    }
    __syncthreads();

    // prologue: KV tile kt0 + Q tile in one cp.async group
    kv_issue_nc(sb, 0, gK + (kvb + kt0 * 64) * DD, gV + (kvb + kt0 * 64) * DD, tid);
    #pragma unroll
    for (int t = 0; t < 16; t++) {
        int idx = tid + t * 256;
        int r = idx >> 5, c = idx & 31;
        cpa16(sb + (uint32_t)(r * 512 + ((c ^ (r & 7)) << 4)),
              gQ + (qbase + r) * DD + c * 8);
    }
    CP_COMMIT();

    float o[32][4];
    #pragma unroll
    for (int i = 0; i < 32; i++)
        #pragma unroll
        for (int j = 0; j < 4; j++) o[i][j] = 0.f;
    float lsum0 = 0.f, lsum1 = 0.f;

    const int rA  = w * 16 + (l & 15);
    const int cA  = l >> 4;
    const int rxA = rA & 7;
    const uint32_t qrow = sb + rA * 512;
    const int rK  = ((l >> 4) << 3) + (l & 7);
    const int cK  = (l >> 3) & 1;
    const int rVb = (l & 7) + ((l >> 3) & 1) * 8;
    const int cV  = l >> 4;
    const int rx  = l & 7;

    #pragma unroll 1
    for (int kt = 0; kt < 16; kt++) {
        const int st = kt & 1;
        if (kt + 1 < 16) {
            kv_issue_nc(sb, st ^ 1, gK + (kvb + (kt0 + kt + 1) * 64) * DD,
                        gV + (kvb + (kt0 + kt + 1) * 64) * DD, tid);
            CP_COMMIT();
            CP_WAIT1();
        } else {
            CP_WAIT0();
        }
        __syncthreads();

        const uint32_t sKb = sb + FL_K0 + st * FL_STG;
        const uint32_t sVb = sb + FL_V0 + st * FL_STG;

        // ---- S = Q K^T  (16 rows x 64 keys per warp) ----
        float s[8][4];
        #pragma unroll
        for (int i = 0; i < 8; i++)
            #pragma unroll
            for (int j = 0; j < 4; j++) s[i][j] = 0.f;

        #pragma unroll
        for (int ks = 0; ks < 16; ks++) {
            uint32_t a[4];
            ldsm4(qrow + (((2 * ks + cA) ^ rxA) << 4), a);
            #pragma unroll
            for (int h = 0; h < 4; h++) {
                uint32_t kh[4];
                ldsm4(sKb + (rK + h * 16) * 512 + (((2 * ks + cK) ^ rx) << 4), kh);
                mma_f16(s[2 * h],     a, kh[0], kh[1]);
                mma_f16(s[2 * h + 1], a, kh[2], kh[3]);
            }
        }

        // ---- per-kb: softmax (exp2, pack) then PV for that kb ----
        // (shortens s/p live ranges; l summed from unquantized e)
        #pragma unroll
        for (int kb = 0; kb < 4; kb++) {
            float e0 = ex2(s[2 * kb][0]),     e1 = ex2(s[2 * kb][1]);
            float e2 = ex2(s[2 * kb][2]),     e3 = ex2(s[2 * kb][3]);
            float e4 = ex2(s[2 * kb + 1][0]), e5 = ex2(s[2 * kb + 1][1]);
            float e6 = ex2(s[2 * kb + 1][2]), e7 = ex2(s[2 * kb + 1][3]);
            lsum0 += (e0 + e1) + (e4 + e5);
            lsum1 += (e2 + e3) + (e6 + e7);
            uint32_t pa[4];
            pa[0] = h2u(__floats2half2_rn(e0, e1));
            pa[1] = h2u(__floats2half2_rn(e2, e3));
            pa[2] = h2u(__floats2half2_rn(e4, e5));
            pa[3] = h2u(__floats2half2_rn(e6, e7));
            #pragma unroll
            for (int g = 0; g < 16; g++) {
                uint32_t v[4];
                ldsm4t(sVb + (rVb + kb * 16) * 512 + (((2 * g + cV) ^ rx) << 4), v);
                mma_f16(o[2 * g],     pa, v[0], v[1]);
                mma_f16(o[2 * g + 1], pa, v[2], v[3]);
            }
        }
        __syncthreads();
    }

    // quad-reduce l partials
    lsum0 += __shfl_xor_sync(0xffffffffu, lsum0, 1);
    lsum0 += __shfl_xor_sync(0xffffffffu, lsum0, 2);
    lsum1 += __shfl_xor_sync(0xffffffffu, lsum1, 1);
    lsum1 += __shfl_xor_sync(0xffffffffu, lsum1, 2);

    const int r0g = (int)(qbase + w * 16 + grp);   // global row of first row

    if (kq < 3) {
        // store O partial + l partial
        #pragma unroll
        for (int nf = 0; nf < 32; nf++) {
            int col = nf * 8 + tid4 * 2;
            size_t i0 = (size_t)r0g * DD + col;
            size_t i1 = (size_t)(r0g + 8) * DD + col;
            *(float2*)&gOp[kq][i0] = make_float2(o[nf][0], o[nf][1]);
            *(float2*)&gOp[kq][i1] = make_float2(o[nf][2], o[nf][3]);
        }
        if (tid4 == 0) {
            gLp[kq][r0g]     = lsum0;
            gLp[kq][r0g + 8] = lsum1;
        }
        __threadfence();
        __syncthreads();
        if (tid == 0) atomicAdd(&tileDone[tile], 1);
    } else {
        // final unit: wait for peers (all lower bids), merge, normalize, store
        if (tid == 0) {
            spin_on(tileDone + tile, 3);
            __threadfence();
        }
        __syncthreads();

        float l0 = lsum0 + gLp[0][r0g]     + gLp[1][r0g]     + gLp[2][r0g];
        float l1 = lsum1 + gLp[0][r0g + 8] + gLp[1][r0g + 8] + gLp[2][r0g + 8];
        const float inv0 = 1.f / l0, inv1 = 1.f / l1;

        #pragma unroll
        for (int nf = 0; nf < 32; nf++) {
            int col = nf * 8 + tid4 * 2;
            size_t i0 = (size_t)r0g * DD + col;
            size_t i1 = (size_t)(r0g + 8) * DD + col;
            float2 a = make_float2(o[nf][0], o[nf][1]);
            float2 c = make_float2(o[nf][2], o[nf][3]);
            #pragma unroll
            for (int k = 0; k < 3; k++) {
                float2 pa = *(const float2*)&gOp[k][i0];
                float2 pc = *(const float2*)&gOp[k][i1];
                a.x += pa.x; a.y += pa.y;
                c.x += pc.x; c.y += pc.y;
            }
            *(float2*)(out + i0) = make_float2(a.x * inv0, a.y * inv0);
            *(float2*)(out + i1) = make_float2(c.x * inv1, c.y * inv1);
        }
    }
}

// ---------------------------------------------------------------------------
extern "C" void kernel_launch(void* const* d_in, const int* in_sizes, int n_in,
                              void* d_out, int out_size)
{
    const float* x  = (const float*)d_in[0];
    const float* Wq = (const float*)d_in[1];
    const float* bq = (const float*)d_in[2];
    const float* Wk = (const float*)d_in[3];
    const float* bk = (const float*)d_in[4];
    const float* Wv = (const float*)d_in[5];
    const float* bv = (const float*)d_in[6];
    float* out = (float*)d_out;

    cudaFuncSetAttribute(mega, cudaFuncAttributeMaxDynamicSharedMemorySize,
                         MEGA_SMEM);

    convert_all<<<CV_GRID, 256>>>(x, Wq, Wk, Wv);
    mega<<<768 + 1024, 256, MEGA_SMEM>>>(bq, bk, bv, out);
}